// round 2
// baseline (speedup 1.0000x reference)
#include <cuda_runtime.h>

// Problem constants
#define Nn 4
#define Pp 2048
#define Dd 512
#define Hh 8
#define HDv 64
#define NHv (Nn*Hh)              // 32
#define ROWSv (Nn*Pp*Hh)         // 65536
#define SCALE 0.04419417382415922f   // 1/sqrt(512)

// Scratch (device globals; no allocations allowed)
static __device__ float g_q[Nn*Pp*Dd];
static __device__ float g_k[Nn*Pp*Dd];
static __device__ float g_v[Nn*Pp*Dd];
static __device__ float g_oattn[Nn*Pp*Dd];
static __device__ float g_rowmax[ROWSv];
static __device__ float g_rowsum[ROWSv];
static __device__ float g_attn_scratch[NHv*Pp*Pp];   // fallback if d_out lacks attention
static __device__ float g_out_scratch[Nn*Pp*Dd];     // fallback if d_out lacks out

#define FMA16(acc, a, b)                                     \
  acc[0][0] += a.x*b.x; acc[0][1] += a.x*b.y;                \
  acc[0][2] += a.x*b.z; acc[0][3] += a.x*b.w;                \
  acc[1][0] += a.y*b.x; acc[1][1] += a.y*b.y;                \
  acc[1][2] += a.y*b.z; acc[1][3] += a.y*b.w;                \
  acc[2][0] += a.z*b.x; acc[2][1] += a.z*b.y;                \
  acc[2][2] += a.z*b.z; acc[2][3] += a.z*b.w;                \
  acc[3][0] += a.w*b.x; acc[3][1] += a.w*b.y;                \
  acc[3][2] += a.w*b.z; acc[3][3] += a.w*b.w;

// ---------------------------------------------------------------------------
// K1: QKV projection.  X is (65536, 64) rows (n,p,h contiguous); q/k/v = X @ W^T
// ---------------------------------------------------------------------------
__global__ __launch_bounds__(256) void k_qkv(
    const float* __restrict__ x,
    const float* __restrict__ Wq, const float* __restrict__ Wk,
    const float* __restrict__ Wv)
{
    __shared__ __align__(16) float Xst[64][68];   // [d][row]
    __shared__ __align__(16) float Wt[64][68];    // [d][e]
    const int r0  = blockIdx.x * 64;
    const int tid = threadIdx.x;

    for (int i = tid; i < 4096; i += 256) {
        int r = i >> 6, d = i & 63;
        Xst[d][r] = x[(size_t)(r0 + r) * 64 + d];
    }

    const int tx = tid & 15, ty = tid >> 4;

    const float* Ws[3] = {Wq, Wk, Wv};
    float* outs[3] = {g_q, g_k, g_v};

    for (int m = 0; m < 3; m++) {
        __syncthreads();                 // also makes Xst visible on m==0
        for (int i = tid; i < 4096; i += 256) {
            int e = i >> 6, d = i & 63;
            Wt[d][e] = Ws[m][i];         // W[e*64+d]
        }
        __syncthreads();

        float acc[4][4] = {};
        #pragma unroll 8
        for (int d = 0; d < 64; d++) {
            float4 a = *(const float4*)&Xst[d][ty * 4];
            float4 b = *(const float4*)&Wt[d][tx * 4];
            FMA16(acc, a, b);
        }
        float* o = outs[m];
        #pragma unroll
        for (int i2 = 0; i2 < 4; i2++) {
            float4 v4 = make_float4(acc[i2][0], acc[i2][1], acc[i2][2], acc[i2][3]);
            *(float4*)&o[(size_t)(r0 + ty * 4 + i2) * 64 + tx * 4] = v4;
        }
    }
}

// ---------------------------------------------------------------------------
// K2: energy = scale * Q @ K^T per (n,h); written raw into attention buffer.
// grid = (ktile=32, qtile=32, nh=32)
// ---------------------------------------------------------------------------
__global__ __launch_bounds__(256) void k_energy(float* __restrict__ attn)
{
    __shared__ __align__(16) float Qst[64][68];   // [d][q]
    __shared__ __align__(16) float Kst[64][68];   // [d][k]
    const int nh = blockIdx.z;
    const int n  = nh >> 3, h = nh & 7;
    const int q0 = blockIdx.y * 64, k0 = blockIdx.x * 64;
    const int tid = threadIdx.x;

    const float* Qb = g_q + (size_t)n * Pp * Dd + h * 64;
    const float* Kb = g_k + (size_t)n * Pp * Dd + h * 64;

    for (int i = tid; i < 4096; i += 256) {
        int r = i >> 6, d = i & 63;
        Qst[d][r] = Qb[(size_t)(q0 + r) * Dd + d];
        Kst[d][r] = Kb[(size_t)(k0 + r) * Dd + d];
    }
    __syncthreads();

    const int tx = tid & 15, ty = tid >> 4;
    float acc[4][4] = {};
    #pragma unroll 8
    for (int d = 0; d < 64; d++) {
        float4 a = *(const float4*)&Qst[d][ty * 4];
        float4 b = *(const float4*)&Kst[d][tx * 4];
        FMA16(acc, a, b);
    }

    float* erow = attn + ((size_t)nh * Pp + q0) * Pp + k0;
    #pragma unroll
    for (int i2 = 0; i2 < 4; i2++) {
        float4 v4 = make_float4(acc[i2][0] * SCALE, acc[i2][1] * SCALE,
                                acc[i2][2] * SCALE, acc[i2][3] * SCALE);
        *(float4*)&erow[(size_t)(ty * 4 + i2) * Pp + tx * 4] = v4;
    }
}

// ---------------------------------------------------------------------------
// K3: per-row softmax stats (max + sum of exp). One block per row.
// ---------------------------------------------------------------------------
__global__ __launch_bounds__(256) void k_stats(const float* __restrict__ attn)
{
    __shared__ float red[256];
    const size_t base = (size_t)blockIdx.x * Pp;
    const int tid = threadIdx.x;

    float v[8];
    float m = -1e30f;
    #pragma unroll
    for (int i = 0; i < 8; i++) {
        v[i] = attn[base + tid + i * 256];
        m = fmaxf(m, v[i]);
    }
    red[tid] = m; __syncthreads();
    #pragma unroll
    for (int s = 128; s > 0; s >>= 1) {
        if (tid < s) red[tid] = fmaxf(red[tid], red[tid + s]);
        __syncthreads();
    }
    m = red[0];
    __syncthreads();

    float ssum = 0.f;
    #pragma unroll
    for (int i = 0; i < 8; i++) ssum += __expf(v[i] - m);
    red[tid] = ssum; __syncthreads();
    #pragma unroll
    for (int s = 128; s > 0; s >>= 1) {
        if (tid < s) red[tid] += red[tid + s];
        __syncthreads();
    }
    if (tid == 0) {
        g_rowmax[blockIdx.x] = m;
        g_rowsum[blockIdx.x] = red[0];
    }
}

// ---------------------------------------------------------------------------
// K4: normalize attention in place + O = A @ V (fused).
// grid = (qtile=32, nh=32)
// ---------------------------------------------------------------------------
__global__ __launch_bounds__(256) void k_attnv(float* __restrict__ attn)
{
    __shared__ __align__(16) float Pst[64][68];   // [k][q]
    __shared__ __align__(16) float Vs[64][68];    // [k][e]
    __shared__ float ms[64], is[64];

    const int nh = blockIdx.y;
    const int n  = nh >> 3, h = nh & 7;
    const int q0 = blockIdx.x * 64;
    const int tid = threadIdx.x;
    const size_t rowbase = (size_t)nh * Pp + q0;

    if (tid < 64) {
        ms[tid] = g_rowmax[rowbase + tid];
        is[tid] = 1.0f / g_rowsum[rowbase + tid];
    }

    const float* Vb = g_v + (size_t)n * Pp * Dd + h * 64;
    float* arow = attn + rowbase * Pp;

    const int tx = tid & 15, ty = tid >> 4;
    const int qr = tid >> 2, c0 = (tid & 3) * 16;
    float acc[4][4] = {};

    for (int kt = 0; kt < 32; kt++) {
        __syncthreads();   // smem reuse guard; also publishes ms/is on first iter
        for (int i = tid; i < 4096; i += 256) {
            int kr = i >> 6, e = i & 63;
            Vs[kr][e] = Vb[(size_t)(kt * 64 + kr) * Dd + e];
        }
        const float mm = ms[qr], ii = is[qr];
        float* ap = arow + (size_t)qr * Pp + kt * 64 + c0;
        #pragma unroll
        for (int j = 0; j < 16; j += 4) {
            float4 e4 = *(const float4*)&ap[j];
            float4 p4;
            p4.x = __expf(e4.x - mm) * ii;
            p4.y = __expf(e4.y - mm) * ii;
            p4.z = __expf(e4.z - mm) * ii;
            p4.w = __expf(e4.w - mm) * ii;
            *(float4*)&ap[j] = p4;
            Pst[c0 + j + 0][qr] = p4.x;
            Pst[c0 + j + 1][qr] = p4.y;
            Pst[c0 + j + 2][qr] = p4.z;
            Pst[c0 + j + 3][qr] = p4.w;
        }
        __syncthreads();
        #pragma unroll 8
        for (int k = 0; k < 64; k++) {
            float4 a = *(const float4*)&Pst[k][ty * 4];
            float4 b = *(const float4*)&Vs[k][tx * 4];
            FMA16(acc, a, b);
        }
    }

    float* ob = g_oattn + ((size_t)n * Pp + q0) * Dd + h * 64;
    #pragma unroll
    for (int i2 = 0; i2 < 4; i2++) {
        float4 v4 = make_float4(acc[i2][0], acc[i2][1], acc[i2][2], acc[i2][3]);
        *(float4*)&ob[(size_t)(ty * 4 + i2) * Dd + tx * 4] = v4;
    }
}

// ---------------------------------------------------------------------------
// K5: out = O @ Wo^T + bo.   (8192 x 512) @ (512 x 512)^T
// grid = (ctile=8, rtile=128)
// ---------------------------------------------------------------------------
__global__ __launch_bounds__(256) void k_oproj(
    const float* __restrict__ Wo, const float* __restrict__ bo,
    float* __restrict__ out)
{
    __shared__ __align__(16) float Ast[64][68];   // [d][r]
    __shared__ __align__(16) float Wot[64][68];   // [d][e]
    const int r0 = blockIdx.y * 64, c0 = blockIdx.x * 64;
    const int tid = threadIdx.x;
    const int tx = tid & 15, ty = tid >> 4;

    float acc[4][4] = {};
    for (int kc = 0; kc < 8; kc++) {
        __syncthreads();
        for (int i = tid; i < 4096; i += 256) {
            int r = i >> 6, d = i & 63;
            Ast[d][r] = g_oattn[(size_t)(r0 + r) * Dd + kc * 64 + d];
            Wot[d][r] = Wo[(size_t)(c0 + r) * Dd + kc * 64 + d];
        }
        __syncthreads();
        #pragma unroll 8
        for (int d = 0; d < 64; d++) {
            float4 a = *(const float4*)&Ast[d][ty * 4];
            float4 b = *(const float4*)&Wot[d][tx * 4];
            FMA16(acc, a, b);
        }
    }

    const int c = c0 + tx * 4;
    float4 bb = *(const float4*)&bo[c];
    #pragma unroll
    for (int i2 = 0; i2 < 4; i2++) {
        float4 v4 = make_float4(acc[i2][0] + bb.x, acc[i2][1] + bb.y,
                                acc[i2][2] + bb.z, acc[i2][3] + bb.w);
        *(float4*)&out[(size_t)(r0 + ty * 4 + i2) * Dd + c] = v4;
    }
}

// ---------------------------------------------------------------------------
extern "C" void kernel_launch(void* const* d_in, const int* in_sizes, int n_in,
                              void* d_out, int out_size)
{
    const float* x  = (const float*)d_in[0];
    const float* Wq = (const float*)d_in[1];
    const float* Wk = (const float*)d_in[2];
    const float* Wv = (const float*)d_in[3];
    const float* Wo = (const float*)d_in[4];
    const float* bo = (const float*)d_in[5];

    const long long OUT_E = (long long)Nn * Pp * Dd;          // 4194304
    const long long ATT_E = (long long)NHv * Pp * Pp;         // 134217728
    const long long os = (long long)out_size;

    float* outp;
    float* attnp;
    if (os >= OUT_E + ATT_E) {
        // tuple flattened in reference order: (out, attention)
        outp  = (float*)d_out;
        attnp = (float*)d_out + OUT_E;
    } else if (os == ATT_E) {
        attnp = (float*)d_out;
        cudaGetSymbolAddress((void**)&outp, g_out_scratch);
    } else {
        outp = (float*)d_out;
        cudaGetSymbolAddress((void**)&attnp, g_attn_scratch);
    }

    // K1: QKV projection.  65536 rows / 64 per block.
    k_qkv<<<ROWSv / 64, 256>>>(x, Wq, Wk, Wv);

    // K2: raw scaled energy into the attention buffer.
    k_energy<<<dim3(32, 32, 32), 256>>>(attnp);

    // K3: softmax row stats.
    k_stats<<<ROWSv, 256>>>(attnp);

    // K4: normalize in place + A@V.
    k_attnv<<<dim3(32, 32), 256>>>(attnp);

    // K5: output projection + bias.
    k_oproj<<<dim3(8, 128), 256>>>(Wo, bo, outp);
}

// round 6
// speedup vs baseline: 2.7757x; 2.7757x over previous
#include <cuda_runtime.h>
#include <cuda_bf16.h>
#include <cstdint>

// Problem constants
#define Nn 4
#define Pp 2048
#define Dd 512
#define Hh 8
#define HDv 64
#define NHv (Nn*Hh)              // 32
#define ROWSv (Nn*Pp*Hh)         // 65536
#define SCALE 0.04419417382415922f   // 1/sqrt(512)

// ---------------------------------------------------------------------------
// Device scratch (no allocations allowed)
// ---------------------------------------------------------------------------
static __device__ __nv_bfloat16 g_qh[Nn*Pp*Dd];     // Q hi  [nh][p][64]
static __device__ __nv_bfloat16 g_ql[Nn*Pp*Dd];     // Q lo
static __device__ __nv_bfloat16 g_kh[Nn*Pp*Dd];     // K hi
static __device__ __nv_bfloat16 g_kl[Nn*Pp*Dd];     // K lo
static __device__ __nv_bfloat16 g_vTh[Nn*Pp*Dd];    // V^T hi [nh][e=64][p=2048]
static __device__ __nv_bfloat16 g_vTl[Nn*Pp*Dd];    // V^T lo
static __device__ float g_oattn[Nn*Pp*Dd];
static __device__ float g_rowmax[ROWSv];
static __device__ float g_rowinv[ROWSv];
static __device__ float g_attn_scratch[NHv*Pp*Pp];   // fallback
static __device__ float g_out_scratch[Nn*Pp*Dd];     // fallback

// ---------------------------------------------------------------------------
// mma.sync m16n8k16 bf16 (portable PTX, HMMA on sm_103)
// ---------------------------------------------------------------------------
__device__ __forceinline__ void mma_bf16(float* c, const uint32_t* a,
                                         const uint32_t* b) {
    asm volatile(
        "mma.sync.aligned.m16n8k16.row.col.f32.bf16.bf16.f32 "
        "{%0,%1,%2,%3}, {%4,%5,%6,%7}, {%8,%9}, {%0,%1,%2,%3};"
        : "+f"(c[0]), "+f"(c[1]), "+f"(c[2]), "+f"(c[3])
        : "r"(a[0]), "r"(a[1]), "r"(a[2]), "r"(a[3]),
          "r"(b[0]), "r"(b[1]));
}

__device__ __forceinline__ uint32_t pack2bf(float a, float b) {
    __nv_bfloat162 t = __floats2bfloat162_rn(a, b);
    return *reinterpret_cast<uint32_t*>(&t);
}
__device__ __forceinline__ void packhilo(float a, float b,
                                         uint32_t& hi, uint32_t& lo) {
    float ha = __bfloat162float(__float2bfloat16_rn(a));
    float hb = __bfloat162float(__float2bfloat16_rn(b));
    hi = pack2bf(a, b);
    lo = pack2bf(a - ha, b - hb);
}
__device__ __forceinline__ void split4(float x0, float x1, float x2, float x3,
                                       uint2& hi, uint2& lo) {
    packhilo(x0, x1, hi.x, lo.x);
    packhilo(x2, x3, hi.y, lo.y);
}

#define FMA16(acc, a, b)                                     \
  acc[0][0] += a.x*b.x; acc[0][1] += a.x*b.y;                \
  acc[0][2] += a.x*b.z; acc[0][3] += a.x*b.w;                \
  acc[1][0] += a.y*b.x; acc[1][1] += a.y*b.y;                \
  acc[1][2] += a.y*b.z; acc[1][3] += a.y*b.w;                \
  acc[2][0] += a.z*b.x; acc[2][1] += a.z*b.y;                \
  acc[2][2] += a.z*b.z; acc[2][3] += a.z*b.w;                \
  acc[3][0] += a.w*b.x; acc[3][1] += a.w*b.y;                \
  acc[3][2] += a.w*b.z; acc[3][3] += a.w*b.w;

// ---------------------------------------------------------------------------
// K1: QKV projection (FFMA) -> bf16 hi/lo outputs; V transposed.
// ---------------------------------------------------------------------------
__global__ __launch_bounds__(256) void k_qkv(
    const float* __restrict__ x,
    const float* __restrict__ Wq, const float* __restrict__ Wk,
    const float* __restrict__ Wv)
{
    __shared__ __align__(16) float Xst[64][68];
    __shared__ __align__(16) float Wt[64][68];
    const int r0  = blockIdx.x * 64;
    const int tid = threadIdx.x;

    for (int i = tid; i < 4096; i += 256) {
        int r = i >> 6, d = i & 63;
        Xst[d][r] = x[(size_t)(r0 + r) * 64 + d];
    }

    const int tx = tid & 15, ty = tid >> 4;
    const float* Ws[3] = {Wq, Wk, Wv};

    for (int m = 0; m < 3; m++) {
        __syncthreads();
        for (int i = tid; i < 4096; i += 256) {
            int e = i >> 6, d = i & 63;
            Wt[d][e] = Ws[m][i];
        }
        __syncthreads();

        float acc[4][4] = {};
        #pragma unroll 8
        for (int d = 0; d < 64; d++) {
            float4 a = *(const float4*)&Xst[d][ty * 4];
            float4 b = *(const float4*)&Wt[d][tx * 4];
            FMA16(acc, a, b);
        }

        if (m < 2) {
            __nv_bfloat16* Gh = (m == 0) ? g_qh : g_kh;
            __nv_bfloat16* Gl = (m == 0) ? g_ql : g_kl;
            #pragma unroll
            for (int i2 = 0; i2 < 4; i2++) {
                int r = r0 + ty * 4 + i2;
                int h = r & 7; int np = r >> 3;
                int p = np & 2047; int n_ = np >> 11;
                size_t dst = ((size_t)((n_ * 8 + h) * 2048 + p)) * 64 + tx * 4;
                uint2 hi, lo;
                split4(acc[i2][0], acc[i2][1], acc[i2][2], acc[i2][3], hi, lo);
                *(uint2*)&Gh[dst] = hi;
                *(uint2*)&Gl[dst] = lo;
            }
        } else {
            __syncthreads();
            #pragma unroll
            for (int i2 = 0; i2 < 4; i2++)
                #pragma unroll
                for (int j = 0; j < 4; j++)
                    Xst[tx * 4 + j][ty * 4 + i2] = acc[i2][j];
            __syncthreads();

            int np0 = r0 >> 3;
            int n_ = np0 >> 11;
            int p0 = np0 & 2047;
            #pragma unroll
            for (int pr = 0; pr < 2; pr++) {
                int pair = tid + pr * 256;       // (h, e)
                int h = pair >> 6, e = pair & 63;
                float v[8];
                #pragma unroll
                for (int pi = 0; pi < 8; pi++) v[pi] = Xst[e][pi * 8 + h];
                uint2 hi0, lo0, hi1, lo1;
                split4(v[0], v[1], v[2], v[3], hi0, lo0);
                split4(v[4], v[5], v[6], v[7], hi1, lo1);
                uint4 hi4 = make_uint4(hi0.x, hi0.y, hi1.x, hi1.y);
                uint4 lo4 = make_uint4(lo0.x, lo0.y, lo1.x, lo1.y);
                size_t base = ((size_t)((n_ * 8 + h) * 64 + e)) * 2048 + p0;
                *(uint4*)&g_vTh[base] = hi4;
                *(uint4*)&g_vTl[base] = lo4;
            }
        }
    }
}

// ---------------------------------------------------------------------------
// K2: softmax row stats via register-only E = scale*Q@K^T (split bf16 MMA).
// grid = (qb=16, nh=32), 256 threads (8 warps, 16 q-rows each).
// ---------------------------------------------------------------------------
__global__ __launch_bounds__(256) void k_stats_tc()
{
    __shared__ __nv_bfloat16 Kh[128][72];
    __shared__ __nv_bfloat16 Kl[128][72];

    const int tid = threadIdx.x;
    const int w = tid >> 5, lane = tid & 31;
    const int qb = blockIdx.x, nh = blockIdx.y;
    const int q0 = qb * 128;

    // Q fragments for this warp's 16 rows (hi + lo), 64 d.
    uint32_t aqh[16], aql[16];
    {
        const uint32_t* qhp = (const uint32_t*)g_qh;
        const uint32_t* qlp = (const uint32_t*)g_ql;
        int qrow = nh * 2048 + q0 + w * 16;
        #pragma unroll
        for (int dc = 0; dc < 4; dc++)
            #pragma unroll
            for (int r = 0; r < 4; r++) {
                int row = qrow + (lane >> 2) + 8 * (r & 1);
                int col2 = dc * 8 + (lane & 3) + 4 * (r >> 1);
                aqh[dc * 4 + r] = qhp[(size_t)row * 32 + col2];
                aql[dc * 4 + r] = qlp[(size_t)row * 32 + col2];
            }
    }

    float m0 = -1e30f, s0 = 0.f, m1 = -1e30f, s1 = 0.f;

    for (int kc = 0; kc < 2048; kc += 128) {
        // load K chunk (hi/lo) [128][64]
        #pragma unroll
        for (int it = 0; it < 4; it++) {
            int idx = it * 256 + tid;
            int row = idx >> 3, c8 = idx & 7;
            const uint4* sh = (const uint4*)g_kh + (size_t)(nh * 2048 + kc + row) * 8 + c8;
            const uint4* sl = (const uint4*)g_kl + (size_t)(nh * 2048 + kc + row) * 8 + c8;
            *(uint4*)&Kh[row][c8 * 8] = *sh;
            *(uint4*)&Kl[row][c8 * 8] = *sl;
        }
        __syncthreads();

        #pragma unroll 4
        for (int n8 = 0; n8 < 16; n8++) {
            float c[4] = {0.f, 0.f, 0.f, 0.f};
            int tok = n8 * 8 + (lane >> 2);
            #pragma unroll
            for (int dc = 0; dc < 4; dc++) {
                int dcol = dc * 16 + (lane & 3) * 2;
                uint32_t bh[2], bl[2];
                bh[0] = *(const uint32_t*)&Kh[tok][dcol];
                bh[1] = *(const uint32_t*)&Kh[tok][dcol + 8];
                bl[0] = *(const uint32_t*)&Kl[tok][dcol];
                bl[1] = *(const uint32_t*)&Kl[tok][dcol + 8];
                mma_bf16(c, &aqh[dc * 4], bh);
                mma_bf16(c, &aqh[dc * 4], bl);
                mma_bf16(c, &aql[dc * 4], bh);
            }
            float e0 = c[0] * SCALE, e1 = c[1] * SCALE;
            float e2 = c[2] * SCALE, e3 = c[3] * SCALE;
            float lm0 = fmaxf(e0, e1), lm1 = fmaxf(e2, e3);
            float nm0 = fmaxf(m0, lm0), nm1 = fmaxf(m1, lm1);
            s0 = s0 * __expf(m0 - nm0) + __expf(e0 - nm0) + __expf(e1 - nm0);
            s1 = s1 * __expf(m1 - nm1) + __expf(e2 - nm1) + __expf(e3 - nm1);
            m0 = nm0; m1 = nm1;
        }
        __syncthreads();
    }

    // merge across the 4 lanes sharing a row
    #pragma unroll
    for (int off = 1; off <= 2; off <<= 1) {
        float om = __shfl_xor_sync(0xFFFFFFFFu, m0, off);
        float os = __shfl_xor_sync(0xFFFFFFFFu, s0, off);
        float nm = fmaxf(m0, om);
        s0 = s0 * __expf(m0 - nm) + os * __expf(om - nm);
        m0 = nm;
        om = __shfl_xor_sync(0xFFFFFFFFu, m1, off);
        os = __shfl_xor_sync(0xFFFFFFFFu, s1, off);
        nm = fmaxf(m1, om);
        s1 = s1 * __expf(m1 - nm) + os * __expf(om - nm);
        m1 = nm;
    }
    if ((lane & 3) == 0) {
        int grow0 = nh * 2048 + q0 + w * 16 + (lane >> 2);
        g_rowmax[grow0] = m0;
        g_rowinv[grow0] = 1.0f / s0;
        g_rowmax[grow0 + 8] = m1;
        g_rowinv[grow0 + 8] = 1.0f / s1;
    }
}

// ---------------------------------------------------------------------------
// K3: recompute E, normalize -> write attention; chain P into A@V (split MMA).
// grid = (qb=16, nh=32), 256 threads (8 warps, 16 q-rows each).
// ---------------------------------------------------------------------------
__global__ __launch_bounds__(256) void k_attnv_tc(float* __restrict__ attn)
{
    __shared__ __nv_bfloat16 Kh[64][72];
    __shared__ __nv_bfloat16 Kl[64][72];
    __shared__ __nv_bfloat16 Vh[64][72];
    __shared__ __nv_bfloat16 Vl[64][72];

    const int tid = threadIdx.x;
    const int w = tid >> 5, lane = tid & 31;
    const int qb = blockIdx.x, nh = blockIdx.y;
    const int q0 = qb * 128;
    const int n_ = nh >> 3, h = nh & 7;

    uint32_t aqh[16], aql[16];
    {
        const uint32_t* qhp = (const uint32_t*)g_qh;
        const uint32_t* qlp = (const uint32_t*)g_ql;
        int qrow = nh * 2048 + q0 + w * 16;
        #pragma unroll
        for (int dc = 0; dc < 4; dc++)
            #pragma unroll
            for (int r = 0; r < 4; r++) {
                int row = qrow + (lane >> 2) + 8 * (r & 1);
                int col2 = dc * 8 + (lane & 3) + 4 * (r >> 1);
                aqh[dc * 4 + r] = qhp[(size_t)row * 32 + col2];
                aql[dc * 4 + r] = qlp[(size_t)row * 32 + col2];
            }
    }

    const int r0g = nh * 2048 + q0 + w * 16 + (lane >> 2);
    const float m0 = g_rowmax[r0g],     i0 = g_rowinv[r0g];
    const float m1 = g_rowmax[r0g + 8], i1 = g_rowinv[r0g + 8];

    float* arow0 = attn + (size_t)r0g * 2048;
    float* arow1 = attn + (size_t)(r0g + 8) * 2048;

    float o[8][4];
    #pragma unroll
    for (int ne = 0; ne < 8; ne++)
        #pragma unroll
        for (int j = 0; j < 4; j++) o[ne][j] = 0.f;

    for (int kc = 0; kc < 2048; kc += 64) {
        // load K + V^T chunks (hi/lo), 64x64 each
        #pragma unroll
        for (int it = 0; it < 2; it++) {
            int idx = it * 256 + tid;
            int row = idx >> 3, c8 = idx & 7;
            *(uint4*)&Kh[row][c8 * 8] =
                *((const uint4*)g_kh + (size_t)(nh * 2048 + kc + row) * 8 + c8);
            *(uint4*)&Kl[row][c8 * 8] =
                *((const uint4*)g_kl + (size_t)(nh * 2048 + kc + row) * 8 + c8);
            *(uint4*)&Vh[row][c8 * 8] =
                *((const uint4*)g_vTh + (size_t)(nh * 64 + row) * 256 + (kc >> 3) + c8);
            *(uint4*)&Vl[row][c8 * 8] =
                *((const uint4*)g_vTl + (size_t)(nh * 64 + row) * 256 + (kc >> 3) + c8);
        }
        __syncthreads();

        // E tiles (8 x n8) — identical MMA sequence to k_stats_tc
        float ec[8][4];
        #pragma unroll
        for (int n8 = 0; n8 < 8; n8++) {
            float* c = ec[n8];
            c[0] = c[1] = c[2] = c[3] = 0.f;
            int tok = n8 * 8 + (lane >> 2);
            #pragma unroll
            for (int dc = 0; dc < 4; dc++) {
                int dcol = dc * 16 + (lane & 3) * 2;
                uint32_t bh[2], bl[2];
                bh[0] = *(const uint32_t*)&Kh[tok][dcol];
                bh[1] = *(const uint32_t*)&Kh[tok][dcol + 8];
                bl[0] = *(const uint32_t*)&Kl[tok][dcol];
                bl[1] = *(const uint32_t*)&Kl[tok][dcol + 8];
                mma_bf16(c, &aqh[dc * 4], bh);
                mma_bf16(c, &aqh[dc * 4], bl);
                mma_bf16(c, &aql[dc * 4], bh);
            }
        }

        // normalize + write P + build A-fragments for A@V
        uint32_t pah[16], pal[16];
        #pragma unroll
        for (int n8 = 0; n8 < 8; n8++) {
            float p0 = __expf(ec[n8][0] * SCALE - m0) * i0;
            float p1 = __expf(ec[n8][1] * SCALE - m0) * i0;
            float p2 = __expf(ec[n8][2] * SCALE - m1) * i1;
            float p3 = __expf(ec[n8][3] * SCALE - m1) * i1;
            int col = kc + n8 * 8 + (lane & 3) * 2;
            *(float2*)&arow0[col] = make_float2(p0, p1);
            *(float2*)&arow1[col] = make_float2(p2, p3);
            int base = (n8 >> 1) * 4 + (n8 & 1) * 2;
            packhilo(p0, p1, pah[base],     pal[base]);
            packhilo(p2, p3, pah[base + 1], pal[base + 1]);
        }

        // A@V: contraction over 64 tokens = 4 k16 chunks
        #pragma unroll
        for (int kk = 0; kk < 4; kk++) {
            #pragma unroll
            for (int ne = 0; ne < 8; ne++) {
                int e = ne * 8 + (lane >> 2);
                int tcol = kk * 16 + (lane & 3) * 2;
                uint32_t bh[2], bl[2];
                bh[0] = *(const uint32_t*)&Vh[e][tcol];
                bh[1] = *(const uint32_t*)&Vh[e][tcol + 8];
                bl[0] = *(const uint32_t*)&Vl[e][tcol];
                bl[1] = *(const uint32_t*)&Vl[e][tcol + 8];
                mma_bf16(o[ne], &pah[kk * 4], bh);
                mma_bf16(o[ne], &pah[kk * 4], bl);
                mma_bf16(o[ne], &pal[kk * 4], bh);
            }
        }
        __syncthreads();
    }

    // epilogue: O rows
    int p = q0 + w * 16 + (lane >> 2);
    float* ob0 = g_oattn + ((size_t)(n_ * 2048 + p)) * 512 + h * 64;
    float* ob1 = ob0 + (size_t)8 * 512;
    #pragma unroll
    for (int ne = 0; ne < 8; ne++) {
        int col = ne * 8 + (lane & 3) * 2;
        *(float2*)&ob0[col] = make_float2(o[ne][0], o[ne][1]);
        *(float2*)&ob1[col] = make_float2(o[ne][2], o[ne][3]);
    }
}

// ---------------------------------------------------------------------------
// K5: out = O @ Wo^T + bo (FFMA)
// ---------------------------------------------------------------------------
__global__ __launch_bounds__(256) void k_oproj(
    const float* __restrict__ Wo, const float* __restrict__ bo,
    float* __restrict__ out)
{
    __shared__ __align__(16) float Ast[64][68];
    __shared__ __align__(16) float Wot[64][68];
    const int r0 = blockIdx.y * 64, c0 = blockIdx.x * 64;
    const int tid = threadIdx.x;
    const int tx = tid & 15, ty = tid >> 4;

    float acc[4][4] = {};
    for (int kc = 0; kc < 8; kc++) {
        __syncthreads();
        for (int i = tid; i < 4096; i += 256) {
            int r = i >> 6, d = i & 63;
            Ast[d][r] = g_oattn[(size_t)(r0 + r) * Dd + kc * 64 + d];
            Wot[d][r] = Wo[(size_t)(c0 + r) * Dd + kc * 64 + d];
        }
        __syncthreads();
        #pragma unroll 8
        for (int d = 0; d < 64; d++) {
            float4 a = *(const float4*)&Ast[d][ty * 4];
            float4 b = *(const float4*)&Wot[d][tx * 4];
            FMA16(acc, a, b);
        }
    }

    const int c = c0 + tx * 4;
    float4 bb = *(const float4*)&bo[c];
    #pragma unroll
    for (int i2 = 0; i2 < 4; i2++) {
        float4 v4 = make_float4(acc[i2][0] + bb.x, acc[i2][1] + bb.y,
                                acc[i2][2] + bb.z, acc[i2][3] + bb.w);
        *(float4*)&out[(size_t)(r0 + ty * 4 + i2) * Dd + c] = v4;
    }
}

// ---------------------------------------------------------------------------
extern "C" void kernel_launch(void* const* d_in, const int* in_sizes, int n_in,
                              void* d_out, int out_size)
{
    const float* x  = (const float*)d_in[0];
    const float* Wq = (const float*)d_in[1];
    const float* Wk = (const float*)d_in[2];
    const float* Wv = (const float*)d_in[3];
    const float* Wo = (const float*)d_in[4];
    const float* bo = (const float*)d_in[5];

    const long long OUT_E = (long long)Nn * Pp * Dd;      // 4194304
    const long long ATT_E = (long long)NHv * Pp * Pp;     // 134217728
    const long long os = (long long)out_size;

    float* outp;
    float* attnp;
    if (os >= OUT_E + ATT_E) {
        outp  = (float*)d_out;
        attnp = (float*)d_out + OUT_E;
    } else if (os == ATT_E) {
        attnp = (float*)d_out;
        cudaGetSymbolAddress((void**)&outp, g_out_scratch);
    } else {
        outp = (float*)d_out;
        cudaGetSymbolAddress((void**)&attnp, g_attn_scratch);
    }

    k_qkv<<<ROWSv / 64, 256>>>(x, Wq, Wk, Wv);
    k_stats_tc<<<dim3(16, 32), 256>>>();
    k_attnv_tc<<<dim3(16, 32), 256>>>(attnp);
    k_oproj<<<dim3(8, 128), 256>>>(Wo, bo, outp);
}